// round 7
// baseline (speedup 1.0000x reference)
#include <cuda_runtime.h>
#include <math.h>

#define BB 8
#define TT 1024
#define DD 1024
#define HH 16
#define AD 64
#define BT (BB*TT)      /* 8192 */
#define HA (HH*AD)      /* 1024 */
#define NEDGE 262144
#define BIASDIM 32
#define FBIG 3.402823466e+38f

// ---------------- scratch (no allocations allowed) ----------------
__device__ float g_q[BT*HA];
__device__ float g_k[BT*HA];
__device__ float g_v[BT*HA];
__device__ float g_ctx[BT*HA];
__device__ float g_ksum[BT*HH];
__device__ float g_bs[BB*TT*TT];
__device__ int   g_winner[BB*TT*TT];
__device__ float g_alpha[(size_t)BB*HH*TT*TT];
__device__ float g_proj[BIASDIM];
__device__ int   g_is64;

// ---------------- dtype detector for attention_bias ----------------
// int64 little-endian with values < 2^31: every odd int32 word (hi-word) is 0.
__global__ void detect_kernel(const int* __restrict__ ab32) {
    int ok = 1;
    #pragma unroll
    for (int i = 0; i < 64; i++) ok &= (ab32[2 * i + 1] == 0);
    g_is64 = ok;
}

// ---------------- proj[et] = bias_embs[et] . bias_scalar ----------------
__global__ void proj_kernel(const float* __restrict__ embs, const float* __restrict__ scal) {
    int et = threadIdx.x;                       // 32 threads
    if (et >= BIASDIM) return;
    float s = 0.f;
    #pragma unroll
    for (int a = 0; a < AD; a++) s += embs[et * AD + a] * scal[a];
    g_proj[et] = s;
}

// ---------------- generic tiled SGEMM: C[M,N] = A[M,K] @ B[K,N] ----------------
// which_a: 0=ext A, 1=g_ctx.  which_c: 0=g_q, 1=g_k, 2=g_v, 3=ext C.
__global__ void sgemm_kernel(const float* __restrict__ Aext, const float* __restrict__ Bm,
                             float* __restrict__ Cext, int which_a, int which_c,
                             int M, int N, int K) {
    const float* A = (which_a == 1) ? g_ctx : Aext;
    float* C = (which_c == 0) ? g_q : (which_c == 1) ? g_k : (which_c == 2) ? g_v : Cext;
    __shared__ float As[16][65];   // [kk][m]
    __shared__ float Bs[16][65];   // [kk][n]
    const int tid = threadIdx.x;
    const int tx = tid & 15, ty = tid >> 4;
    const int m0 = blockIdx.y * 64, n0 = blockIdx.x * 64;
    float acc[4][4] = {};
    for (int k0 = 0; k0 < K; k0 += 16) {
        #pragma unroll
        for (int i = 0; i < 4; i++) {
            int idx = tid + i * 256;          // 0..1023
            int m  = idx >> 4, ka = idx & 15;
            As[ka][m] = A[(size_t)(m0 + m) * K + k0 + ka];
            int n  = idx & 63, kb = idx >> 6;
            Bs[kb][n] = Bm[(size_t)(k0 + kb) * N + n0 + n];
        }
        __syncthreads();
        #pragma unroll
        for (int kk = 0; kk < 16; kk++) {
            float ar[4], br[4];
            #pragma unroll
            for (int i = 0; i < 4; i++) ar[i] = As[kk][ty + 16 * i];
            #pragma unroll
            for (int j = 0; j < 4; j++) br[j] = Bs[kk][tx + 16 * j];
            #pragma unroll
            for (int i = 0; i < 4; i++)
                #pragma unroll
                for (int j = 0; j < 4; j++)
                    acc[i][j] += ar[i] * br[j];
        }
        __syncthreads();
    }
    #pragma unroll
    for (int i = 0; i < 4; i++)
        #pragma unroll
        for (int j = 0; j < 4; j++)
            C[(size_t)(m0 + ty + 16 * i) * N + n0 + tx + 16 * j] = acc[i][j];
}

// ---------------- ksum[b,t,h] = sum_a k[b,t,h,a] ----------------
__global__ void ksum_kernel() {
    int idx = blockIdx.x * blockDim.x + threadIdx.x;   // bt*H + h
    if (idx >= BT * HH) return;
    int bt = idx / HH, h = idx % HH;
    const float4* p = reinterpret_cast<const float4*>(&g_k[(size_t)bt * HA + h * AD]);
    float s = 0.f;
    #pragma unroll
    for (int i = 0; i < AD / 4; i++) { float4 v4 = p[i]; s += v4.x + v4.y + v4.z + v4.w; }
    g_ksum[idx] = s;
}

// ---------------- zero dense bias + winner scratch ----------------
__global__ void zero_bs_kernel() {
    int i = blockIdx.x * blockDim.x + threadIdx.x;
    if (i < BB * TT * TT) { g_bs[i] = 0.f; g_winner[i] = -1; }
}

// ---------------- decode edge e ----------------
__device__ __forceinline__ bool decode_edge(const int* __restrict__ ab32, int e,
                                            int& et, int& b, int& qi, int& ki) {
    if (g_is64) {
        const long long* ab = (const long long*)ab32;
        et = (int)ab[4 * e + 0];
        b  = (int)ab[4 * e + 1];
        qi = (int)ab[4 * e + 2];
        ki = (int)ab[4 * e + 3];
    } else {
        et = ab32[4 * e + 0];
        b  = ab32[4 * e + 1];
        qi = ab32[4 * e + 2];
        ki = ab32[4 * e + 3];
    }
    return !((unsigned)et >= BIASDIM || (unsigned)b >= BB ||
             (unsigned)qi >= TT || (unsigned)ki >= TT);
}

// ---------------- scatter pass 1: deterministic last-edge-wins via atomicMax ----
__global__ void scatter_pass1_kernel(const int* __restrict__ ab32) {
    int e = blockIdx.x * blockDim.x + threadIdx.x;
    if (e >= NEDGE) return;
    int et, b, qi, ki;
    if (!decode_edge(ab32, e, et, b, qi, ki)) return;
    atomicMax(&g_winner[((size_t)b * TT + qi) * TT + ki], e);
}

// ---------------- scatter pass 2: winning edge writes its bias value ----------
__global__ void scatter_pass2_kernel(const int* __restrict__ ab32) {
    int e = blockIdx.x * blockDim.x + threadIdx.x;
    if (e >= NEDGE) return;
    int et, b, qi, ki;
    if (!decode_edge(ab32, e, et, b, qi, ki)) return;
    size_t slot = ((size_t)b * TT + qi) * TT + ki;
    if (g_winner[slot] == e) g_bs[slot] = g_proj[et];
}

// ---------------- scores: alpha[b,h,q,k] = (q.k + bs*ksum)*0.125 - mask*BIG ----------------
__global__ void scores_kernel(const float* __restrict__ masks) {
    __shared__ float Qs[64][65];   // [a][q]
    __shared__ float Ks[64][65];   // [a][k]
    const int z = blockIdx.z;                 // b*H + h
    const int b = z >> 4, h = z & 15;
    const int q0 = blockIdx.y * 64, k0 = blockIdx.x * 64;
    const int tid = threadIdx.x, tx = tid & 15, ty = tid >> 4;
    const float* qbase = g_q + (size_t)(b * TT + q0) * HA + h * AD;
    const float* kbase = g_k + (size_t)(b * TT + k0) * HA + h * AD;
    #pragma unroll
    for (int i = 0; i < 16; i++) {
        int idx = tid + i * 256;              // 0..4095
        int t = idx >> 6, a = idx & 63;
        Qs[a][t] = qbase[(size_t)t * HA + a];
        Ks[a][t] = kbase[(size_t)t * HA + a];
    }
    __syncthreads();
    float acc[4][4] = {};
    #pragma unroll
    for (int a = 0; a < 64; a++) {
        float qr[4], kr[4];
        #pragma unroll
        for (int i = 0; i < 4; i++) qr[i] = Qs[a][ty + 16 * i];
        #pragma unroll
        for (int j = 0; j < 4; j++) kr[j] = Ks[a][tx + 16 * j];
        #pragma unroll
        for (int i = 0; i < 4; i++)
            #pragma unroll
            for (int j = 0; j < 4; j++)
                acc[i][j] += qr[i] * kr[j];
    }
    #pragma unroll
    for (int i = 0; i < 4; i++) {
        int qi = q0 + ty + 16 * i;
        #pragma unroll
        for (int j = 0; j < 4; j++) {
            int ki = k0 + tx + 16 * j;
            float bias = g_bs[((size_t)b * TT + qi) * TT + ki] *
                         g_ksum[(size_t)(b * TT + ki) * HH + h];
            float val = (acc[i][j] + bias) * 0.125f;   // 1/sqrt(64)
            val -= masks[((size_t)b * TT + qi) * TT + ki] * FBIG;
            g_alpha[((size_t)z * TT + qi) * TT + ki] = val;
        }
    }
}

// ---------------- softmax over last dim, in place, one block per row ----------------
__global__ void softmax_kernel() {
    __shared__ float smax[8];
    __shared__ float ssum[8];
    float* p = g_alpha + (size_t)blockIdx.x * TT;
    const int tid = threadIdx.x;                 // 256
    const int lane = tid & 31, wid = tid >> 5;
    float x[4];
    #pragma unroll
    for (int i = 0; i < 4; i++) x[i] = p[tid + 256 * i];
    float mx = fmaxf(fmaxf(x[0], x[1]), fmaxf(x[2], x[3]));
    #pragma unroll
    for (int o = 16; o; o >>= 1) mx = fmaxf(mx, __shfl_xor_sync(0xffffffffu, mx, o));
    if (lane == 0) smax[wid] = mx;
    __syncthreads();
    mx = smax[0];
    #pragma unroll
    for (int w = 1; w < 8; w++) mx = fmaxf(mx, smax[w]);
    float s = 0.f;
    #pragma unroll
    for (int i = 0; i < 4; i++) { x[i] = expf(x[i] - mx); s += x[i]; }
    #pragma unroll
    for (int o = 16; o; o >>= 1) s += __shfl_xor_sync(0xffffffffu, s, o);
    if (lane == 0) ssum[wid] = s;
    __syncthreads();
    float tot = 0.f;
    #pragma unroll
    for (int w = 0; w < 8; w++) tot += ssum[w];
    float inv = 1.0f / tot;
    #pragma unroll
    for (int i = 0; i < 4; i++) p[tid + 256 * i] = x[i] * inv;
}

// ---------------- context: ctx[b,q,h,a] = sum_k alpha[b,h,q,k] * v[b,k,h,a] ----------------
__global__ void context_kernel() {
    __shared__ float Ps[32][65];   // [kk][q]
    __shared__ float Vs[32][65];   // [kk][a]
    const int z = blockIdx.y;                 // b*H + h
    const int b = z >> 4, h = z & 15;
    const int q0 = blockIdx.x * 64;
    const int tid = threadIdx.x, tx = tid & 15, ty = tid >> 4;
    const float* prow  = g_alpha + ((size_t)z * TT + q0) * TT;
    const float* vbase = g_v + (size_t)(b * TT) * HA + h * AD;
    float acc[4][4] = {};
    for (int k0 = 0; k0 < TT; k0 += 32) {
        #pragma unroll
        for (int i = 0; i < 8; i++) {
            int idx = tid + i * 256;          // 0..2047
            int t = idx >> 5, ka = idx & 31;
            Ps[ka][t] = prow[(size_t)t * TT + k0 + ka];
            int a = idx & 63, kb = idx >> 6;  // kb 0..31
            Vs[kb][a] = vbase[(size_t)(k0 + kb) * HA + a];
        }
        __syncthreads();
        #pragma unroll
        for (int kk = 0; kk < 32; kk++) {
            float pr[4], vr[4];
            #pragma unroll
            for (int i = 0; i < 4; i++) pr[i] = Ps[kk][ty + 16 * i];
            #pragma unroll
            for (int j = 0; j < 4; j++) vr[j] = Vs[kk][tx + 16 * j];
            #pragma unroll
            for (int i = 0; i < 4; i++)
                #pragma unroll
                for (int j = 0; j < 4; j++)
                    acc[i][j] += pr[i] * vr[j];
        }
        __syncthreads();
    }
    #pragma unroll
    for (int i = 0; i < 4; i++)
        #pragma unroll
        for (int j = 0; j < 4; j++)
            g_ctx[(size_t)(b * TT + q0 + ty + 16 * i) * HA + h * AD + tx + 16 * j] = acc[i][j];
}

// ---------------- launch ----------------
extern "C" void kernel_launch(void* const* d_in, const int* in_sizes, int n_in,
                              void* d_out, int out_size) {
    const float* states     = (const float*)d_in[0];
    const float* key_states = (const float*)d_in[1];
    const float* masks      = (const float*)d_in[2];
    const int*   ab32       = (const int*)d_in[3];
    const float* Wq         = (const float*)d_in[4];
    const float* Wk         = (const float*)d_in[5];
    const float* Wv         = (const float*)d_in[6];
    const float* Wout       = (const float*)d_in[7];
    const float* embs       = (const float*)d_in[8];
    const float* scal       = (const float*)d_in[9];
    float* out              = (float*)d_out;

    dim3 gemm_grid(HA / 64, BT / 64);   // (16, 128)

    // QKV projections (write device globals, selected by which_c)
    sgemm_kernel<<<gemm_grid, 256>>>(states,     Wq, nullptr, 0, 0, BT, HA, DD);
    sgemm_kernel<<<gemm_grid, 256>>>(key_states, Wk, nullptr, 0, 1, BT, HA, DD);
    sgemm_kernel<<<gemm_grid, 256>>>(key_states, Wv, nullptr, 0, 2, BT, HA, DD);

    // ksum
    ksum_kernel<<<(BT * HH + 255) / 256, 256>>>();

    // edge-bias dtype detect + per-type projection + deterministic scatter
    detect_kernel<<<1, 1>>>(ab32);
    proj_kernel<<<1, 32>>>(embs, scal);
    zero_bs_kernel<<<(BB * TT * TT + 255) / 256, 256>>>();
    scatter_pass1_kernel<<<(NEDGE + 255) / 256, 256>>>(ab32);
    scatter_pass2_kernel<<<(NEDGE + 255) / 256, 256>>>(ab32);

    // scores + softmax
    dim3 sc_grid(TT / 64, TT / 64, BB * HH);   // (16, 16, 128)
    scores_kernel<<<sc_grid, 256>>>(masks);
    softmax_kernel<<<BB * HH * TT, 256>>>();

    // context
    dim3 cx_grid(TT / 64, BB * HH);            // (16, 128)
    context_kernel<<<cx_grid, 256>>>();

    // output projection (A = g_ctx via which_a=1, C = d_out)
    sgemm_kernel<<<gemm_grid, 256>>>(nullptr, Wout, out, 1, 3, BT, DD, HA);
}